// round 12
// baseline (speedup 1.0000x reference)
#include <cuda_runtime.h>
#include <cuda_bf16.h>

#define U 64
#define M 8192
#define D 64
#define CHUNK 512
#define NCHUNK (M / CHUNK)   // 16
#define BLOCK 256
#define NWARP (BLOCK / 32)   // 8
#define SLOTS_PER_WARP (CHUNK / NWARP)   // 64

#define NEG_INF_F __int_as_float(0xff800000)

// Device scratch (no allocations allowed)
__device__ float g_cmax[U * NCHUNK];
__device__ float g_csum[U * NCHUNK];

// ---------------------------------------------------------------------------
// Kernel 1: scores + per-chunk softmax stats (unchanged R10 hot path)
// + block c==0 zeroes this unit's outputs (k_out accumulates atomically).
// grid (NCHUNK, U), block 256.
// ---------------------------------------------------------------------------
__global__ void __launch_bounds__(BLOCK)
k_scores(const float* __restrict__ q,      // [U, D]
         const float* __restrict__ keys,   // [U, M, D]
         const int*   __restrict__ mask,   // [U, M] (0/1 int32)
         const float* __restrict__ tmpr,   // [U, 1]
         float* __restrict__ scores,       // [U, M]
         float* __restrict__ outp)         // [U, D] -> zeroed here
{
    __shared__ float s_s[CHUNK];
    __shared__ float s_red[NWARP];

    const int u = blockIdx.y, c = blockIdx.x;
    const int tid = threadIdx.x, lane = tid & 31, warp = tid >> 5;
    const int sub = lane & 15, half = lane >> 4;
    const int m0 = c * CHUNK;

    if (c == 0 && tid < D / 4)
        ((float4*)(outp + u * D))[tid] = make_float4(0.0f, 0.0f, 0.0f, 0.0f);

    const float4 q4 = ((const float4*)(q + u * D))[sub];

    const int base_slot = warp * SLOTS_PER_WARP;
    #pragma unroll 4
    for (int i = 0; i < SLOTS_PER_WARP / 4; i++) {           // 16 iterations
        const int j0 = base_slot + 4 * i + half;             // slots j0, j0+2
        const size_t r0 = ((size_t)(u * M + m0 + j0))     * D;
        const size_t r1 = ((size_t)(u * M + m0 + j0 + 2)) * D;
        const float4 a = __ldcs((const float4*)(keys + r0) + sub);
        const float4 b = __ldcs((const float4*)(keys + r1) + sub);
        float p0 = a.x * q4.x + a.y * q4.y + a.z * q4.z + a.w * q4.w;
        float p1 = b.x * q4.x + b.y * q4.y + b.z * q4.z + b.w * q4.w;
        #pragma unroll
        for (int o = 1; o < 16; o <<= 1) {
            p0 += __shfl_xor_sync(0xffffffffu, p0, o);
            p1 += __shfl_xor_sync(0xffffffffu, p1, o);
        }
        if (sub == 0) {
            s_s[j0]     = p0;
            s_s[j0 + 2] = p1;
        }
    }
    __syncthreads();

    const float t = tmpr[u];
    const int j2 = tid * 2;
    const float2 sv = *(const float2*)&s_s[j2];
    const int2  mk = ((const int2*)(mask + u * M + m0))[tid];
    float s0 = ((mk.x != 0) ? -1e9f : sv.x) / t;
    float s1 = ((mk.y != 0) ? -1e9f : sv.y) / t;
    ((float2*)(scores + (size_t)u * M + m0))[tid] = make_float2(s0, s1);

    float lm = fmaxf(s0, s1);
    #pragma unroll
    for (int o = 16; o > 0; o >>= 1) lm = fmaxf(lm, __shfl_xor_sync(0xffffffffu, lm, o));
    if (lane == 0) s_red[warp] = lm;
    __syncthreads();
    float cmax = s_red[0];
    #pragma unroll
    for (int w = 1; w < NWARP; w++) cmax = fmaxf(cmax, s_red[w]);
    __syncthreads();

    float ls = __expf(s0 - cmax) + __expf(s1 - cmax);
    #pragma unroll
    for (int o = 16; o > 0; o >>= 1) ls += __shfl_xor_sync(0xffffffffu, ls, o);
    if (lane == 0) s_red[warp] = ls;
    __syncthreads();
    if (tid == 0) {
        float sm = 0.0f;
        #pragma unroll
        for (int w = 0; w < NWARP; w++) sm += s_red[w];
        g_cmax[u * NCHUNK + c] = cmax;
        g_csum[u * NCHUNK + c] = sm;
    }
}

// ---------------------------------------------------------------------------
// Kernel 2: recombine -> weights, weighted memory sum + fused memories copy,
// atomicAdd epilogue into outputs.
// CHANGE vs R10: the flash recombine (gmax/gsum) is computed by ONE warp
// (16 expf per CTA) and broadcast via smem, instead of redundantly by all
// 256 threads (4096 expf per CTA) — removes ~33us of chip-wide MUFU
// serialization.
// grid (NCHUNK, U), block 256.
// ---------------------------------------------------------------------------
__global__ void __launch_bounds__(BLOCK)
k_out(const float* __restrict__ mem,       // [U, M, D]
      float* __restrict__ weights,         // [U, M] (scores on entry)
      float* __restrict__ memout,          // [U, M, D]
      float* __restrict__ outp)            // [U, D] (zeroed by k_scores)
{
    __shared__ float  s_w[CHUNK];
    __shared__ float  s_stats[2];          // {gmax, inv}
    __shared__ float4 s_acc[NWARP][32];

    const int u = blockIdx.y, c = blockIdx.x;
    const int tid = threadIdx.x, lane = tid & 31, warp = tid >> 5;
    const int sub = lane & 15, half = lane >> 4;
    const int m0 = c * CHUNK;

    // ---- warp 0 only: global softmax stats (16 expf per CTA total) ----
    if (warp == 0) {
        const float cm = (lane < NCHUNK) ? g_cmax[u * NCHUNK + lane] : NEG_INF_F;
        const float cs = (lane < NCHUNK) ? g_csum[u * NCHUNK + lane] : 0.0f;
        float gm = cm;
        #pragma unroll
        for (int o = 16; o > 0; o >>= 1) gm = fmaxf(gm, __shfl_xor_sync(0xffffffffu, gm, o));
        float term = (lane < NCHUNK) ? cs * __expf(cm - gm) : 0.0f;
        #pragma unroll
        for (int o = 16; o > 0; o >>= 1) term += __shfl_xor_sync(0xffffffffu, term, o);
        if (lane == 0) {
            s_stats[0] = gm;
            s_stats[1] = 1.0f / term;
        }
    }
    __syncthreads();
    const float gmax = s_stats[0];
    const float inv  = s_stats[1];

    // ---- Phase 1: chunk weights, coalesced (scores likely L2-hot) ----
    const int j2 = tid * 2;
    const float2 sv = ((const float2*)(weights + (size_t)u * M + m0))[tid];
    const float w0 = __expf(sv.x - gmax) * inv;
    const float w1 = __expf(sv.y - gmax) * inv;
    s_w[j2]     = w0;
    s_w[j2 + 1] = w1;
    __stcs((float2*)(weights + (size_t)u * M + m0) + tid, make_float2(w0, w1));
    __syncthreads();

    // ---- Phase 2: stream memories once: weighted sum + fused copy ----
    float4 acc0 = make_float4(0.0f, 0.0f, 0.0f, 0.0f);
    float4 acc1 = make_float4(0.0f, 0.0f, 0.0f, 0.0f);
    const int base_slot = warp * SLOTS_PER_WARP;
    #pragma unroll 4
    for (int i = 0; i < SLOTS_PER_WARP / 4; i++) {
        const int j0 = base_slot + 4 * i + half;
        const size_t r0 = ((size_t)(u * M + m0 + j0))     * D;
        const size_t r1 = ((size_t)(u * M + m0 + j0 + 2)) * D;
        const float4 a = __ldcs((const float4*)(mem + r0) + sub);
        const float4 b = __ldcs((const float4*)(mem + r1) + sub);
        const float wa = s_w[j0];
        const float wb = s_w[j0 + 2];
        acc0.x = fmaf(wa, a.x, acc0.x);
        acc0.y = fmaf(wa, a.y, acc0.y);
        acc0.z = fmaf(wa, a.z, acc0.z);
        acc0.w = fmaf(wa, a.w, acc0.w);
        acc1.x = fmaf(wb, b.x, acc1.x);
        acc1.y = fmaf(wb, b.y, acc1.y);
        acc1.z = fmaf(wb, b.z, acc1.z);
        acc1.w = fmaf(wb, b.w, acc1.w);
        __stcs((float4*)(memout + r0) + sub, a);             // fused copy
        __stcs((float4*)(memout + r1) + sub, b);
    }
    acc0.x += acc1.x; acc0.y += acc1.y; acc0.z += acc1.z; acc0.w += acc1.w;
    s_acc[warp][lane] = acc0;
    __syncthreads();

    // ---- Phase 3: chunk partial -> outputs via atomicAdd ----
    if (tid < 16) {
        float4 tsum = make_float4(0.0f, 0.0f, 0.0f, 0.0f);
        #pragma unroll
        for (int w = 0; w < NWARP; w++) {
            #pragma unroll
            for (int h = 0; h < 2; h++) {
                const float4 v = s_acc[w][h * 16 + tid];
                tsum.x += v.x; tsum.y += v.y; tsum.z += v.z; tsum.w += v.w;
            }
        }
        float* dst = outp + u * D + tid * 4;
        atomicAdd(dst + 0, tsum.x);
        atomicAdd(dst + 1, tsum.y);
        atomicAdd(dst + 2, tsum.z);
        atomicAdd(dst + 3, tsum.w);
    }
}

extern "C" void kernel_launch(void* const* d_in, const int* in_sizes, int n_in,
                              void* d_out, int out_size)
{
    const float* attention  = (const float*)d_in[0];  // [U, D]
    const float* attentions = (const float*)d_in[1];  // [U, M, D]
    const float* memories   = (const float*)d_in[2];  // [U, M, D]
    const float* tmpr       = (const float*)d_in[3];  // [U, 1]
    const int*   mask       = (const int*)  d_in[4];  // [U, M]

    float* out          = (float*)d_out;
    float* out_outputs  = out;                        // [U, D]
    float* out_weights  = out + U * D;                // [U, M]
    float* out_memories = out + U * D + U * M;        // [U, M, D]

    dim3 grid(NCHUNK, U);
    k_scores<<<grid, BLOCK>>>(attention, attentions, mask, tmpr,
                              out_weights, out_outputs);
    k_out<<<grid, BLOCK>>>(memories, out_weights, out_memories, out_outputs);
}

// round 13
// speedup vs baseline: 1.0487x; 1.0487x over previous
#include <cuda_runtime.h>
#include <cuda_bf16.h>

#define U 64
#define M 8192
#define D 64
#define CHUNK 512
#define NCHUNK (M / CHUNK)   // 16
#define BLOCK 256
#define NWARP (BLOCK / 32)   // 8
#define SLOTS_PER_WARP (CHUNK / NWARP)   // 64

#define NEG_INF_F __int_as_float(0xff800000)

// Device scratch (no allocations allowed)
__device__ float g_cmax[U * NCHUNK];
__device__ float g_csum[U * NCHUNK];

// ---------------------------------------------------------------------------
// Kernel 1: scores + per-chunk softmax stats.
// grid (NCHUNK, U), block 256, min 8 CTAs/SM (single wave at grid=1024).
// ---------------------------------------------------------------------------
__global__ void __launch_bounds__(BLOCK, 8)
k_scores(const float* __restrict__ q,      // [U, D]
         const float* __restrict__ keys,   // [U, M, D]
         const int*   __restrict__ mask,   // [U, M] (0/1 int32)
         const float* __restrict__ tmpr,   // [U, 1]
         float* __restrict__ scores,       // [U, M]
         float* __restrict__ outp)         // [U, D] -> zeroed here
{
    __shared__ float s_s[CHUNK];
    __shared__ float s_red[NWARP];

    const int u = blockIdx.y, c = blockIdx.x;
    const int tid = threadIdx.x, lane = tid & 31, warp = tid >> 5;
    const int sub = lane & 15, half = lane >> 4;
    const int m0 = c * CHUNK;

    if (c == 0 && tid < D / 4)
        ((float4*)(outp + u * D))[tid] = make_float4(0.0f, 0.0f, 0.0f, 0.0f);

    const float4 q4 = ((const float4*)(q + u * D))[sub];

    const int base_slot = warp * SLOTS_PER_WARP;
    #pragma unroll 4
    for (int i = 0; i < SLOTS_PER_WARP / 4; i++) {           // 16 iterations
        const int j0 = base_slot + 4 * i + half;             // slots j0, j0+2
        const size_t r0 = ((size_t)(u * M + m0 + j0))     * D;
        const size_t r1 = ((size_t)(u * M + m0 + j0 + 2)) * D;
        const float4 a = __ldcs((const float4*)(keys + r0) + sub);
        const float4 b = __ldcs((const float4*)(keys + r1) + sub);
        float p0 = a.x * q4.x + a.y * q4.y + a.z * q4.z + a.w * q4.w;
        float p1 = b.x * q4.x + b.y * q4.y + b.z * q4.z + b.w * q4.w;
        #pragma unroll
        for (int o = 1; o < 16; o <<= 1) {
            p0 += __shfl_xor_sync(0xffffffffu, p0, o);
            p1 += __shfl_xor_sync(0xffffffffu, p1, o);
        }
        if (sub == 0) {
            s_s[j0]     = p0;
            s_s[j0 + 2] = p1;
        }
    }
    __syncthreads();

    const float t = tmpr[u];
    const int j2 = tid * 2;
    const float2 sv = *(const float2*)&s_s[j2];
    const int2  mk = ((const int2*)(mask + u * M + m0))[tid];
    float s0 = ((mk.x != 0) ? -1e9f : sv.x) / t;
    float s1 = ((mk.y != 0) ? -1e9f : sv.y) / t;
    ((float2*)(scores + (size_t)u * M + m0))[tid] = make_float2(s0, s1);

    float lm = fmaxf(s0, s1);
    #pragma unroll
    for (int o = 16; o > 0; o >>= 1) lm = fmaxf(lm, __shfl_xor_sync(0xffffffffu, lm, o));
    if (lane == 0) s_red[warp] = lm;
    __syncthreads();
    float cmax = s_red[0];
    #pragma unroll
    for (int w = 1; w < NWARP; w++) cmax = fmaxf(cmax, s_red[w]);
    __syncthreads();

    float ls = __expf(s0 - cmax) + __expf(s1 - cmax);
    #pragma unroll
    for (int o = 16; o > 0; o >>= 1) ls += __shfl_xor_sync(0xffffffffu, ls, o);
    if (lane == 0) s_red[warp] = ls;
    __syncthreads();
    if (tid == 0) {
        float sm = 0.0f;
        #pragma unroll
        for (int w = 0; w < NWARP; w++) sm += s_red[w];
        g_cmax[u * NCHUNK + c] = cmax;
        g_csum[u * NCHUNK + c] = sm;
    }
}

// ---------------------------------------------------------------------------
// Kernel 2: recombine -> weights, weighted memory sum + fused memories copy,
// atomicAdd epilogue into outputs.
// CHANGE vs R12: __launch_bounds__(256, 8) pins regs <= 32 so all 1024 CTAs
// fit in ONE wave (was 34 regs -> ~6 CTAs/SM -> 2 waves with a starved tail).
// grid (NCHUNK, U), block 256.
// ---------------------------------------------------------------------------
__global__ void __launch_bounds__(BLOCK, 8)
k_out(const float* __restrict__ mem,       // [U, M, D]
      float* __restrict__ weights,         // [U, M] (scores on entry)
      float* __restrict__ memout,          // [U, M, D]
      float* __restrict__ outp)            // [U, D] (zeroed by k_scores)
{
    __shared__ float  s_w[CHUNK];
    __shared__ float  s_stats[2];          // {gmax, inv}
    __shared__ float4 s_acc[NWARP][32];

    const int u = blockIdx.y, c = blockIdx.x;
    const int tid = threadIdx.x, lane = tid & 31, warp = tid >> 5;
    const int sub = lane & 15, half = lane >> 4;
    const int m0 = c * CHUNK;

    // ---- warp 0 only: global softmax stats (16 expf per CTA total) ----
    if (warp == 0) {
        const float cm = (lane < NCHUNK) ? g_cmax[u * NCHUNK + lane] : NEG_INF_F;
        const float cs = (lane < NCHUNK) ? g_csum[u * NCHUNK + lane] : 0.0f;
        float gm = cm;
        #pragma unroll
        for (int o = 16; o > 0; o >>= 1) gm = fmaxf(gm, __shfl_xor_sync(0xffffffffu, gm, o));
        float term = (lane < NCHUNK) ? cs * __expf(cm - gm) : 0.0f;
        #pragma unroll
        for (int o = 16; o > 0; o >>= 1) term += __shfl_xor_sync(0xffffffffu, term, o);
        if (lane == 0) {
            s_stats[0] = gm;
            s_stats[1] = 1.0f / term;
        }
    }
    __syncthreads();
    const float gmax = s_stats[0];
    const float inv  = s_stats[1];

    // ---- Phase 1: chunk weights, coalesced (scores likely L2-hot) ----
    const int j2 = tid * 2;
    const float2 sv = ((const float2*)(weights + (size_t)u * M + m0))[tid];
    const float w0 = __expf(sv.x - gmax) * inv;
    const float w1 = __expf(sv.y - gmax) * inv;
    s_w[j2]     = w0;
    s_w[j2 + 1] = w1;
    __stcs((float2*)(weights + (size_t)u * M + m0) + tid, make_float2(w0, w1));
    __syncthreads();

    // ---- Phase 2: stream memories once: weighted sum + fused copy ----
    float4 acc0 = make_float4(0.0f, 0.0f, 0.0f, 0.0f);
    float4 acc1 = make_float4(0.0f, 0.0f, 0.0f, 0.0f);
    const int base_slot = warp * SLOTS_PER_WARP;
    #pragma unroll 4
    for (int i = 0; i < SLOTS_PER_WARP / 4; i++) {
        const int j0 = base_slot + 4 * i + half;
        const size_t r0 = ((size_t)(u * M + m0 + j0))     * D;
        const size_t r1 = ((size_t)(u * M + m0 + j0 + 2)) * D;
        const float4 a = __ldcs((const float4*)(mem + r0) + sub);
        const float4 b = __ldcs((const float4*)(mem + r1) + sub);
        const float wa = s_w[j0];
        const float wb = s_w[j0 + 2];
        acc0.x = fmaf(wa, a.x, acc0.x);
        acc0.y = fmaf(wa, a.y, acc0.y);
        acc0.z = fmaf(wa, a.z, acc0.z);
        acc0.w = fmaf(wa, a.w, acc0.w);
        acc1.x = fmaf(wb, b.x, acc1.x);
        acc1.y = fmaf(wb, b.y, acc1.y);
        acc1.z = fmaf(wb, b.z, acc1.z);
        acc1.w = fmaf(wb, b.w, acc1.w);
        __stcs((float4*)(memout + r0) + sub, a);             // fused copy
        __stcs((float4*)(memout + r1) + sub, b);
    }
    acc0.x += acc1.x; acc0.y += acc1.y; acc0.z += acc1.z; acc0.w += acc1.w;
    s_acc[warp][lane] = acc0;
    __syncthreads();

    // ---- Phase 3: chunk partial -> outputs via atomicAdd ----
    if (tid < 16) {
        float4 tsum = make_float4(0.0f, 0.0f, 0.0f, 0.0f);
        #pragma unroll
        for (int w = 0; w < NWARP; w++) {
            #pragma unroll
            for (int h = 0; h < 2; h++) {
                const float4 v = s_acc[w][h * 16 + tid];
                tsum.x += v.x; tsum.y += v.y; tsum.z += v.z; tsum.w += v.w;
            }
        }
        float* dst = outp + u * D + tid * 4;
        atomicAdd(dst + 0, tsum.x);
        atomicAdd(dst + 1, tsum.y);
        atomicAdd(dst + 2, tsum.z);
        atomicAdd(dst + 3, tsum.w);
    }
}

extern "C" void kernel_launch(void* const* d_in, const int* in_sizes, int n_in,
                              void* d_out, int out_size)
{
    const float* attention  = (const float*)d_in[0];  // [U, D]
    const float* attentions = (const float*)d_in[1];  // [U, M, D]
    const float* memories   = (const float*)d_in[2];  // [U, M, D]
    const float* tmpr       = (const float*)d_in[3];  // [U, 1]
    const int*   mask       = (const int*)  d_in[4];  // [U, M]

    float* out          = (float*)d_out;
    float* out_outputs  = out;                        // [U, D]
    float* out_weights  = out + U * D;                // [U, M]
    float* out_memories = out + U * D + U * M;        // [U, M, D]

    dim3 grid(NCHUNK, U);
    k_scores<<<grid, BLOCK>>>(attention, attentions, mask, tmpr,
                              out_weights, out_outputs);
    k_out<<<grid, BLOCK>>>(memories, out_weights, out_memories, out_outputs);
}

// round 14
// speedup vs baseline: 1.0927x; 1.0420x over previous
#include <cuda_runtime.h>
#include <cuda_bf16.h>

#define U 64
#define M 8192
#define D 64
#define CHUNK 512
#define NCHUNK (M / CHUNK)   // 16
#define BLOCK 256
#define NWARP (BLOCK / 32)   // 8
#define SLOTS_PER_WARP (CHUNK / NWARP)   // 64

#define NEG_INF_F __int_as_float(0xff800000)

// Device scratch (no allocations allowed)
__device__ float g_cmax[U * NCHUNK];
__device__ float g_csum[U * NCHUNK];

// ---------------------------------------------------------------------------
// Kernel 1: scores + per-chunk softmax stats. (unchanged from R13 73.0us)
// grid (NCHUNK, U), block 256, min 8 CTAs/SM (single wave at grid=1024).
// ---------------------------------------------------------------------------
__global__ void __launch_bounds__(BLOCK, 8)
k_scores(const float* __restrict__ q,      // [U, D]
         const float* __restrict__ keys,   // [U, M, D]
         const int*   __restrict__ mask,   // [U, M] (0/1 int32)
         const float* __restrict__ tmpr,   // [U, 1]
         float* __restrict__ scores,       // [U, M]
         float* __restrict__ outp)         // [U, D] -> zeroed here
{
    __shared__ float s_s[CHUNK];
    __shared__ float s_red[NWARP];

    const int u = blockIdx.y, c = blockIdx.x;
    const int tid = threadIdx.x, lane = tid & 31, warp = tid >> 5;
    const int sub = lane & 15, half = lane >> 4;
    const int m0 = c * CHUNK;

    if (c == 0 && tid < D / 4)
        ((float4*)(outp + u * D))[tid] = make_float4(0.0f, 0.0f, 0.0f, 0.0f);

    const float4 q4 = ((const float4*)(q + u * D))[sub];

    const int base_slot = warp * SLOTS_PER_WARP;
    #pragma unroll 4
    for (int i = 0; i < SLOTS_PER_WARP / 4; i++) {           // 16 iterations
        const int j0 = base_slot + 4 * i + half;             // slots j0, j0+2
        const size_t r0 = ((size_t)(u * M + m0 + j0))     * D;
        const size_t r1 = ((size_t)(u * M + m0 + j0 + 2)) * D;
        const float4 a = __ldcs((const float4*)(keys + r0) + sub);
        const float4 b = __ldcs((const float4*)(keys + r1) + sub);
        float p0 = a.x * q4.x + a.y * q4.y + a.z * q4.z + a.w * q4.w;
        float p1 = b.x * q4.x + b.y * q4.y + b.z * q4.z + b.w * q4.w;
        #pragma unroll
        for (int o = 1; o < 16; o <<= 1) {
            p0 += __shfl_xor_sync(0xffffffffu, p0, o);
            p1 += __shfl_xor_sync(0xffffffffu, p1, o);
        }
        if (sub == 0) {
            s_s[j0]     = p0;
            s_s[j0 + 2] = p1;
        }
    }
    __syncthreads();

    const float t = tmpr[u];
    const int j2 = tid * 2;
    const float2 sv = *(const float2*)&s_s[j2];
    const int2  mk = ((const int2*)(mask + u * M + m0))[tid];
    float s0 = ((mk.x != 0) ? -1e9f : sv.x) / t;
    float s1 = ((mk.y != 0) ? -1e9f : sv.y) / t;
    ((float2*)(scores + (size_t)u * M + m0))[tid] = make_float2(s0, s1);

    float lm = fmaxf(s0, s1);
    #pragma unroll
    for (int o = 16; o > 0; o >>= 1) lm = fmaxf(lm, __shfl_xor_sync(0xffffffffu, lm, o));
    if (lane == 0) s_red[warp] = lm;
    __syncthreads();
    float cmax = s_red[0];
    #pragma unroll
    for (int w = 1; w < NWARP; w++) cmax = fmaxf(cmax, s_red[w]);
    __syncthreads();

    float ls = __expf(s0 - cmax) + __expf(s1 - cmax);
    #pragma unroll
    for (int o = 16; o > 0; o >>= 1) ls += __shfl_xor_sync(0xffffffffu, ls, o);
    if (lane == 0) s_red[warp] = ls;
    __syncthreads();
    if (tid == 0) {
        float sm = 0.0f;
        #pragma unroll
        for (int w = 0; w < NWARP; w++) sm += s_red[w];
        g_cmax[u * NCHUNK + c] = cmax;
        g_csum[u * NCHUNK + c] = sm;
    }
}

// ---------------------------------------------------------------------------
// Kernel 2: recombine -> weights, weighted memory sum + fused memories copy,
// atomicAdd epilogue.
// CHANGE vs R13: phase 2 batches 4 independent LDG.128 before the 4 STG.128
// each iteration (read-MLP x2 between store bursts; longer same-direction
// DRAM runs). Launch bounds relaxed (waves proven irrelevant for k_out).
// grid (NCHUNK, U), block 256.
// ---------------------------------------------------------------------------
__global__ void __launch_bounds__(BLOCK)
k_out(const float* __restrict__ mem,       // [U, M, D]
      float* __restrict__ weights,         // [U, M] (scores on entry)
      float* __restrict__ memout,          // [U, M, D]
      float* __restrict__ outp)            // [U, D] (zeroed by k_scores)
{
    __shared__ float  s_w[CHUNK];
    __shared__ float  s_stats[2];          // {gmax, inv}
    __shared__ float4 s_acc[NWARP][32];

    const int u = blockIdx.y, c = blockIdx.x;
    const int tid = threadIdx.x, lane = tid & 31, warp = tid >> 5;
    const int sub = lane & 15, half = lane >> 4;
    const int m0 = c * CHUNK;

    // ---- warp 0 only: global softmax stats (16 expf per CTA total) ----
    if (warp == 0) {
        const float cm = (lane < NCHUNK) ? g_cmax[u * NCHUNK + lane] : NEG_INF_F;
        const float cs = (lane < NCHUNK) ? g_csum[u * NCHUNK + lane] : 0.0f;
        float gm = cm;
        #pragma unroll
        for (int o = 16; o > 0; o >>= 1) gm = fmaxf(gm, __shfl_xor_sync(0xffffffffu, gm, o));
        float term = (lane < NCHUNK) ? cs * __expf(cm - gm) : 0.0f;
        #pragma unroll
        for (int o = 16; o > 0; o >>= 1) term += __shfl_xor_sync(0xffffffffu, term, o);
        if (lane == 0) {
            s_stats[0] = gm;
            s_stats[1] = 1.0f / term;
        }
    }
    __syncthreads();
    const float gmax = s_stats[0];
    const float inv  = s_stats[1];

    // ---- Phase 1: chunk weights, coalesced (scores likely L2-hot) ----
    const int j2 = tid * 2;
    const float2 sv = ((const float2*)(weights + (size_t)u * M + m0))[tid];
    const float w0 = __expf(sv.x - gmax) * inv;
    const float w1 = __expf(sv.y - gmax) * inv;
    s_w[j2]     = w0;
    s_w[j2 + 1] = w1;
    __stcs((float2*)(weights + (size_t)u * M + m0) + tid, make_float2(w0, w1));
    __syncthreads();

    // ---- Phase 2: stream memories once: weighted sum + fused copy ----
    float4 acc0 = make_float4(0.0f, 0.0f, 0.0f, 0.0f);
    float4 acc1 = make_float4(0.0f, 0.0f, 0.0f, 0.0f);
    float4 acc2 = make_float4(0.0f, 0.0f, 0.0f, 0.0f);
    float4 acc3 = make_float4(0.0f, 0.0f, 0.0f, 0.0f);
    const int base_slot = warp * SLOTS_PER_WARP;
    #pragma unroll
    for (int i = 0; i < SLOTS_PER_WARP / 8; i++) {           // 8 iterations
        const int j0 = base_slot + 8 * i + half;             // j0,+2,+4,+6
        const size_t r0 = ((size_t)(u * M + m0 + j0))     * D;
        const size_t r1 = ((size_t)(u * M + m0 + j0 + 2)) * D;
        const size_t r2 = ((size_t)(u * M + m0 + j0 + 4)) * D;
        const size_t r3 = ((size_t)(u * M + m0 + j0 + 6)) * D;
        const float4 a = __ldcs((const float4*)(mem + r0) + sub);
        const float4 b = __ldcs((const float4*)(mem + r1) + sub);
        const float4 d = __ldcs((const float4*)(mem + r2) + sub);
        const float4 e = __ldcs((const float4*)(mem + r3) + sub);
        const float wa = s_w[j0];
        const float wb = s_w[j0 + 2];
        const float wd = s_w[j0 + 4];
        const float we = s_w[j0 + 6];
        acc0.x = fmaf(wa, a.x, acc0.x); acc0.y = fmaf(wa, a.y, acc0.y);
        acc0.z = fmaf(wa, a.z, acc0.z); acc0.w = fmaf(wa, a.w, acc0.w);
        acc1.x = fmaf(wb, b.x, acc1.x); acc1.y = fmaf(wb, b.y, acc1.y);
        acc1.z = fmaf(wb, b.z, acc1.z); acc1.w = fmaf(wb, b.w, acc1.w);
        acc2.x = fmaf(wd, d.x, acc2.x); acc2.y = fmaf(wd, d.y, acc2.y);
        acc2.z = fmaf(wd, d.z, acc2.z); acc2.w = fmaf(wd, d.w, acc2.w);
        acc3.x = fmaf(we, e.x, acc3.x); acc3.y = fmaf(we, e.y, acc3.y);
        acc3.z = fmaf(we, e.z, acc3.z); acc3.w = fmaf(we, e.w, acc3.w);
        __stcs((float4*)(memout + r0) + sub, a);             // fused copy
        __stcs((float4*)(memout + r1) + sub, b);
        __stcs((float4*)(memout + r2) + sub, d);
        __stcs((float4*)(memout + r3) + sub, e);
    }
    acc0.x += acc1.x + acc2.x + acc3.x;
    acc0.y += acc1.y + acc2.y + acc3.y;
    acc0.z += acc1.z + acc2.z + acc3.z;
    acc0.w += acc1.w + acc2.w + acc3.w;
    s_acc[warp][lane] = acc0;
    __syncthreads();

    // ---- Phase 3: chunk partial -> outputs via atomicAdd ----
    if (tid < 16) {
        float4 tsum = make_float4(0.0f, 0.0f, 0.0f, 0.0f);
        #pragma unroll
        for (int w = 0; w < NWARP; w++) {
            #pragma unroll
            for (int h = 0; h < 2; h++) {
                const float4 v = s_acc[w][h * 16 + tid];
                tsum.x += v.x; tsum.y += v.y; tsum.z += v.z; tsum.w += v.w;
            }
        }
        float* dst = outp + u * D + tid * 4;
        atomicAdd(dst + 0, tsum.x);
        atomicAdd(dst + 1, tsum.y);
        atomicAdd(dst + 2, tsum.z);
        atomicAdd(dst + 3, tsum.w);
    }
}

extern "C" void kernel_launch(void* const* d_in, const int* in_sizes, int n_in,
                              void* d_out, int out_size)
{
    const float* attention  = (const float*)d_in[0];  // [U, D]
    const float* attentions = (const float*)d_in[1];  // [U, M, D]
    const float* memories   = (const float*)d_in[2];  // [U, M, D]
    const float* tmpr       = (const float*)d_in[3];  // [U, 1]
    const int*   mask       = (const int*)  d_in[4];  // [U, M]

    float* out          = (float*)d_out;
    float* out_outputs  = out;                        // [U, D]
    float* out_weights  = out + U * D;                // [U, M]
    float* out_memories = out + U * D + U * M;        // [U, M, D]

    dim3 grid(NCHUNK, U);
    k_scores<<<grid, BLOCK>>>(attention, attentions, mask, tmpr,
                              out_weights, out_outputs);
    k_out<<<grid, BLOCK>>>(memories, out_weights, out_memories, out_outputs);
}